// round 16
// baseline (speedup 1.0000x reference)
#include <cuda_runtime.h>
#include <cuda_fp16.h>
#include <cstdint>

// Problem constants
#define Bc   16
#define G    8
#define CPER 32
#define CIN  256
#define Jc   64
#define Hc   56
#define Wc   56
#define HW   (Hc * Wc)          // 3136

// Padded-x layout: 58 rows, 60 cols
#define PROWS 58
#define PCOLS 60
#define NPOS  (PROWS * PCOLS)   // 3480

// Tiling: 128 threads (4 warps), block M = 256 spatial (4 output rows), N = 32
#define TILE_OR 4
#define NREAL   ((TILE_OR + 2) * PCOLS)   // 360
#define NPADR   384                        // max read 255+122=377
#define NTHREADS 128
#define NJ      32

// smem rows: 80 B (64 B data + 16 B pad)
#define RSTR    80
#define SM_A    0
#define SM_B    (NPADR * RSTR)            // 30720
#define BT_STR  (NJ * RSTR)               // 2560 per tap
#define SMEM_USED (SM_B + 9 * BT_STR)     // 53760
#define SMEM_BYTES (SMEM_USED + 1024)     // 54784 <= 57344 (228K/4)

#define OSTR 260

// Prepped operands
__device__ __half wgt_f16[G * 9 * Jc * CPER];                       // [g][tap][j][c]
__device__ __half xg_f16[(size_t)Bc * G * NPOS * CPER];             // [b][g][pos][c]

__device__ __forceinline__ uint32_t smem_u32(const void* p) {
    uint32_t a;
    asm("{ .reg .u64 t; cvta.to.shared.u64 t, %1; cvt.u32.u64 %0, t; }"
        : "=r"(a) : "l"(p));
    return a;
}

#define LDMX4(r0, r1, r2, r3, a) \
    asm volatile("ldmatrix.sync.aligned.m8n8.x4.shared.b16 {%0,%1,%2,%3}, [%4];" \
                 : "=r"(r0), "=r"(r1), "=r"(r2), "=r"(r3) : "r"(a))

#define MMA16816(d, a0, a1, a2, a3, b0, b1) \
    asm volatile("mma.sync.aligned.m16n8k16.row.col.f32.f16.f16.f32 " \
                 "{%0,%1,%2,%3}, {%4,%5,%6,%7}, {%8,%9}, {%0,%1,%2,%3};" \
                 : "+f"((d)[0]), "+f"((d)[1]), "+f"((d)[2]), "+f"((d)[3]) \
                 : "r"(a0), "r"(a1), "r"(a2), "r"(a3), "r"(b0), "r"(b1))

// ---- Prep 1: weights fp32 [g][j][c][tap] -> fp16 [g][tap][j][c]
__global__ void __launch_bounds__(256)
prep_weights_kernel(const float* __restrict__ wgt)
{
    int idx = blockIdx.x * 256 + threadIdx.x;
    if (idx >= G * 9 * Jc * CPER) return;
    int c   = idx & 31;
    int j   = (idx >> 5) & 63;
    int tap = (idx >> 11) % 9;
    int g   = idx / (9 * Jc * CPER);
    wgt_f16[idx] = __float2half(wgt[((size_t)(g * Jc + j) * CPER + c) * 9 + tap]);
}

// ---- Prep 2 (no-smem): x -> gathered fp16, zero-padded [b][g][58*60][32c]
__global__ void __launch_bounds__(256)
prep_x_kernel(const float* __restrict__ x, const int* __restrict__ arr)
{
    __shared__ int ch_s[CPER];
    const int tid = threadIdx.x;
    const int g   = blockIdx.x;
    const int b   = blockIdx.z;

    if (tid < CPER) ch_s[tid] = arr[g * CPER + tid];
    __syncthreads();

    int idx = blockIdx.y * 256 + tid;
    int p   = idx >> 2;
    int qc  = idx & 3;
    if (p >= NPOS) return;

    int pr = p / PCOLS;
    int pc = p - pr * PCOLS;
    int xr = pr - 1;
    int xc = pc - 1;

    uint4 v4 = make_uint4(0u, 0u, 0u, 0u);
    if ((unsigned)xr < (unsigned)Hc && (unsigned)xc < (unsigned)Wc) {
        const float* xp = x + (size_t)b * CIN * HW + (size_t)xr * Wc + xc;
        const int* ch = ch_s + qc * 8;
        float f0 = xp[(size_t)ch[0] * HW];
        float f1 = xp[(size_t)ch[1] * HW];
        float f2 = xp[(size_t)ch[2] * HW];
        float f3 = xp[(size_t)ch[3] * HW];
        float f4 = xp[(size_t)ch[4] * HW];
        float f5 = xp[(size_t)ch[5] * HW];
        float f6 = xp[(size_t)ch[6] * HW];
        float f7 = xp[(size_t)ch[7] * HW];
        __half2 h0 = __floats2half2_rn(f0, f1);
        __half2 h1 = __floats2half2_rn(f2, f3);
        __half2 h2 = __floats2half2_rn(f4, f5);
        __half2 h3 = __floats2half2_rn(f6, f7);
        v4.x = *(uint32_t*)&h0;
        v4.y = *(uint32_t*)&h1;
        v4.z = *(uint32_t*)&h2;
        v4.w = *(uint32_t*)&h3;
    }
    uint4* dst = (uint4*)(xg_f16 + ((size_t)(b * G + g)) * NPOS * CPER);
    dst[(size_t)p * 4 + qc] = v4;
}

// ---- Main: implicit-GEMM HMMA, warp tile M=64 x N=32, 4 blocks/SM
__global__ void __launch_bounds__(NTHREADS, 4)
grouped_conv_hmma_kernel(const float* __restrict__ bias,
                         float*       __restrict__ out)
{
    extern __shared__ char dsm[];
    __shared__ float bias_s[NJ];

    const int tid  = threadIdx.x;
    const int wid  = tid >> 5;
    const int lane = tid & 31;

    const int g  = blockIdx.x >> 1;
    const int nh = blockIdx.x & 1;
    const int r0 = blockIdx.y * TILE_OR;
    const int b  = blockIdx.z;

    uint32_t raw  = smem_u32(dsm);
    uint32_t base = (raw + 1023u) & ~1023u;
    char* sm = dsm + (base - raw);
    const uint32_t smA = base + SM_A;
    const uint32_t smB = base + SM_B;

    if (tid < NJ) bias_s[tid] = bias[g * Jc + nh * NJ + tid];

    // ---- Stage A: contiguous copy, 1440 uint4
    {
        const uint4* xsrc = (const uint4*)(xg_f16
            + ((size_t)(b * G + g)) * NPOS * CPER) + (size_t)r0 * PCOLS * 4;
        for (int idx = tid; idx < NREAL * 4; idx += NTHREADS) {
            int n = idx >> 2, q = idx & 3;
            *(uint4*)(sm + SM_A + n * RSTR + q * 16) = xsrc[idx];
        }
    }

    // ---- Stage B: 9 taps x 32 j x 64 B = 1152 uint4
    {
        const uint4* wsrc = (const uint4*)(wgt_f16 + (size_t)g * 9 * Jc * CPER);
        for (int idx = tid; idx < 9 * NJ * 4; idx += NTHREADS) {
            int q   = idx & 3;
            int j   = (idx >> 2) & (NJ - 1);
            int tap = idx >> 7;
            *(uint4*)(sm + SM_B + tap * BT_STR + j * RSTR + q * 16) =
                wsrc[(size_t)(tap * Jc + nh * NJ + j) * 4 + q];
        }
    }
    __syncthreads();

    // ---- MMA mainloop: warp w -> M rows [w*64, w*64+64), N=32
    const int m0 = wid * 64;
    float d[4][4][4];
#pragma unroll
    for (int mt = 0; mt < 4; ++mt)
#pragma unroll
        for (int nt = 0; nt < 4; ++nt)
#pragma unroll
            for (int k = 0; k < 4; ++k) d[mt][nt][k] = 0.0f;

    const int arow  = (lane & 7) + ((lane >> 3) & 1) * 8;
    const int akoff = (lane >> 4) * 16;
    const int brow  = (lane & 7) + (lane >> 4) * 8;
    const int bkoff = ((lane >> 3) & 1) * 16;

    const uint32_t aBase = smA + (m0 + arow) * RSTR + akoff;
    const uint32_t bBase = smB + brow * RSTR + bkoff;

#pragma unroll
    for (int ky = 0; ky < 3; ++ky) {
#pragma unroll
        for (int kx = 0; kx < 3; ++kx) {
            const int dlt = ky * PCOLS + kx;
            const uint32_t btap = bBase + (ky * 3 + kx) * BT_STR;
#pragma unroll
            for (int ks = 0; ks < 2; ++ks) {
                uint32_t af[4][4];
#pragma unroll
                for (int mt = 0; mt < 4; ++mt)
                    LDMX4(af[mt][0], af[mt][1], af[mt][2], af[mt][3],
                          aBase + (mt * 16 + dlt) * RSTR + ks * 32);
                uint32_t bf[4][2];
#pragma unroll
                for (int np = 0; np < 2; ++np)
                    LDMX4(bf[2 * np][0], bf[2 * np][1], bf[2 * np + 1][0], bf[2 * np + 1][1],
                          btap + np * 16 * RSTR + ks * 32);
#pragma unroll
                for (int mt = 0; mt < 4; ++mt)
#pragma unroll
                    for (int nt = 0; nt < 4; ++nt)
                        MMA16816(d[mt][nt], af[mt][0], af[mt][1], af[mt][2], af[mt][3],
                                 bf[nt][0], bf[nt][1]);
            }
        }
    }

    // ---- Epilogue: transpose via smem, vectorized coalesced stores
    __syncthreads();
    float* smO = (float*)sm;               // [32 j][OSTR] = 33280 B
#pragma unroll
    for (int mt = 0; mt < 4; ++mt) {
        int row = m0 + mt * 16 + (lane >> 2);
#pragma unroll
        for (int nt = 0; nt < 4; ++nt) {
            int j = nt * 8 + (lane & 3) * 2;
            if (row < TILE_OR * PCOLS) {
                smO[j * OSTR + row]       = d[mt][nt][0];
                smO[(j + 1) * OSTR + row] = d[mt][nt][1];
            }
            if (row + 8 < TILE_OR * PCOLS) {
                smO[j * OSTR + row + 8]       = d[mt][nt][2];
                smO[(j + 1) * OSTR + row + 8] = d[mt][nt][3];
            }
        }
    }
    __syncthreads();

    {
        float* obase = out + ((size_t)b * (G * Jc) + g * Jc + nh * NJ) * HW
                           + (size_t)r0 * Wc;
        for (int idx = tid; idx < NJ * TILE_OR * 14; idx += NTHREADS) {
            int jl   = idx / (TILE_OR * 14);
            int rem  = idx - jl * (TILE_OR * 14);
            int orow = rem / 14;
            int q    = rem - orow * 14;
            float4 v = *(const float4*)(smO + jl * OSTR + orow * PCOLS + q * 4);
            float bv = bias_s[jl];
            v.x += bv; v.y += bv; v.z += bv; v.w += bv;
            *(float4*)(obase + (size_t)jl * HW + orow * Wc + q * 4) = v;
        }
    }
}

extern "C" void kernel_launch(void* const* d_in, const int* in_sizes, int n_in,
                              void* d_out, int out_size)
{
    const float* x    = (const float*)d_in[0];
    const float* wgt  = (const float*)d_in[1];
    const float* bias = (const float*)d_in[2];
    const int*   arr  = (const int*)d_in[3];
    float* out = (float*)d_out;

    prep_weights_kernel<<<(G * 9 * Jc * CPER + 255) / 256, 256>>>(wgt);
    prep_x_kernel<<<dim3(G, (NPOS * 4 + 255) / 256, Bc), 256>>>(x, arr);

    cudaFuncSetAttribute(grouped_conv_hmma_kernel,
                         cudaFuncAttributeMaxDynamicSharedMemorySize, SMEM_BYTES);

    dim3 grid(G * 2, Hc / TILE_OR, Bc);   // (16, 14, 16) = 3584 blocks
    grouped_conv_hmma_kernel<<<grid, NTHREADS, SMEM_BYTES>>>(bias, out);
}

// round 17
// speedup vs baseline: 1.0375x; 1.0375x over previous
#include <cuda_runtime.h>
#include <cuda_fp16.h>
#include <cstdint>

// Problem constants
#define Bc   16
#define G    8
#define CPER 32
#define CIN  256
#define Jc   64
#define Hc   56
#define Wc   56
#define HW   (Hc * Wc)          // 3136

// Padded-x layout: 58 rows, 60 cols
#define PROWS 58
#define PCOLS 60
#define NPOS  (PROWS * PCOLS)   // 3480

// Tiling: 256 threads (8 warps), block M = 512 spatial (8 output rows), N = 32
#define TILE_OR 8
#define NREAL   ((TILE_OR + 2) * PCOLS)   // 600
#define NPADR   640
#define NTHREADS 256
#define NJ      32

// smem rows: 80 B (64 B data + 16 B pad)
#define RSTR    80
#define SM_A    0
#define SM_B    (NPADR * RSTR)            // 51200
#define BT_STR  (NJ * RSTR)               // 2560 per tap
#define SMEM_USED (SM_B + 9 * BT_STR)     // 74240
#define SMEM_BYTES (SMEM_USED + 1024)     // 75264 <= 77824 (228K/3)

#define OSTR 516

// x-prep y-blocks: ceil(NPOS*4 / 256) = 55; y==55 does the weight slice
#define XP_YBLK 55

// Prepped operands
__device__ __half wgt_f16[G * 9 * Jc * CPER];                       // [g][tap][j][c]
__device__ __half xg_f16[(size_t)Bc * G * NPOS * CPER];             // [b][g][pos][c]

__device__ __forceinline__ uint32_t smem_u32(const void* p) {
    uint32_t a;
    asm("{ .reg .u64 t; cvta.to.shared.u64 t, %1; cvt.u32.u64 %0, t; }"
        : "=r"(a) : "l"(p));
    return a;
}

#define LDMX4(r0, r1, r2, r3, a) \
    asm volatile("ldmatrix.sync.aligned.m8n8.x4.shared.b16 {%0,%1,%2,%3}, [%4];" \
                 : "=r"(r0), "=r"(r1), "=r"(r2), "=r"(r3) : "r"(a))

#define MMA16816(d, a0, a1, a2, a3, b0, b1) \
    asm volatile("mma.sync.aligned.m16n8k16.row.col.f32.f16.f16.f32 " \
                 "{%0,%1,%2,%3}, {%4,%5,%6,%7}, {%8,%9}, {%0,%1,%2,%3};" \
                 : "+f"((d)[0]), "+f"((d)[1]), "+f"((d)[2]), "+f"((d)[3]) \
                 : "r"(a0), "r"(a1), "r"(a2), "r"(a3), "r"(b0), "r"(b1))

// ---- Combined prep: x gather+pad+fp16 (y < 55) and weight transpose (y == 55)
__global__ void __launch_bounds__(256)
prep_kernel(const float* __restrict__ x, const float* __restrict__ wgt,
            const int* __restrict__ arr)
{
    const int tid = threadIdx.x;
    const int g   = blockIdx.x;
    const int b   = blockIdx.z;

    if (blockIdx.y == XP_YBLK) {
        // weight prep: 1152 consecutive elements of wgt_f16 per (g,b)
        int basei = (g * Bc + b) * 1152;
        for (int t = tid; t < 1152; t += 256) {
            int idx = basei + t;
            int c   = idx & 31;
            int j   = (idx >> 5) & 63;
            int tap = (idx >> 11) % 9;
            int gg  = idx / (9 * Jc * CPER);
            wgt_f16[idx] = __float2half(wgt[((size_t)(gg * Jc + j) * CPER + c) * 9 + tap]);
        }
        return;
    }

    __shared__ int ch_s[CPER];
    if (tid < CPER) ch_s[tid] = arr[g * CPER + tid];
    __syncthreads();

    int idx = blockIdx.y * 256 + tid;
    int p   = idx >> 2;
    int qc  = idx & 3;
    if (p >= NPOS) return;

    int pr = p / PCOLS;
    int pc = p - pr * PCOLS;
    int xr = pr - 1;
    int xc = pc - 1;

    uint4 v4 = make_uint4(0u, 0u, 0u, 0u);
    if ((unsigned)xr < (unsigned)Hc && (unsigned)xc < (unsigned)Wc) {
        const float* xp = x + (size_t)b * CIN * HW + (size_t)xr * Wc + xc;
        const int* ch = ch_s + qc * 8;
        float f0 = xp[(size_t)ch[0] * HW];
        float f1 = xp[(size_t)ch[1] * HW];
        float f2 = xp[(size_t)ch[2] * HW];
        float f3 = xp[(size_t)ch[3] * HW];
        float f4 = xp[(size_t)ch[4] * HW];
        float f5 = xp[(size_t)ch[5] * HW];
        float f6 = xp[(size_t)ch[6] * HW];
        float f7 = xp[(size_t)ch[7] * HW];
        __half2 h0 = __floats2half2_rn(f0, f1);
        __half2 h1 = __floats2half2_rn(f2, f3);
        __half2 h2 = __floats2half2_rn(f4, f5);
        __half2 h3 = __floats2half2_rn(f6, f7);
        v4.x = *(uint32_t*)&h0;
        v4.y = *(uint32_t*)&h1;
        v4.z = *(uint32_t*)&h2;
        v4.w = *(uint32_t*)&h3;
    }
    uint4* dst = (uint4*)(xg_f16 + ((size_t)(b * G + g)) * NPOS * CPER);
    dst[(size_t)p * 4 + qc] = v4;
}

// ---- Main: implicit-GEMM HMMA, warp tile M=64 x N=32, 3 blocks/SM (R15 best)
__global__ void __launch_bounds__(NTHREADS, 3)
grouped_conv_hmma_kernel(const float* __restrict__ bias,
                         float*       __restrict__ out)
{
    extern __shared__ char dsm[];
    __shared__ float bias_s[NJ];

    const int tid  = threadIdx.x;
    const int wid  = tid >> 5;
    const int lane = tid & 31;

    const int g  = blockIdx.x >> 1;
    const int nh = blockIdx.x & 1;
    const int r0 = blockIdx.y * TILE_OR;
    const int b  = blockIdx.z;

    uint32_t raw  = smem_u32(dsm);
    uint32_t base = (raw + 1023u) & ~1023u;
    char* sm = dsm + (base - raw);
    const uint32_t smA = base + SM_A;
    const uint32_t smB = base + SM_B;

    if (tid < NJ) bias_s[tid] = bias[g * Jc + nh * NJ + tid];

    // ---- Stage A: contiguous copy, 2400 uint4
    {
        const uint4* xsrc = (const uint4*)(xg_f16
            + ((size_t)(b * G + g)) * NPOS * CPER) + (size_t)r0 * PCOLS * 4;
        for (int idx = tid; idx < NREAL * 4; idx += NTHREADS) {
            int n = idx >> 2, q = idx & 3;
            *(uint4*)(sm + SM_A + n * RSTR + q * 16) = xsrc[idx];
        }
    }

    // ---- Stage B: 9 taps x 32 j x 64 B
    {
        const uint4* wsrc = (const uint4*)(wgt_f16 + (size_t)g * 9 * Jc * CPER);
        for (int idx = tid; idx < 9 * NJ * 4; idx += NTHREADS) {
            int q   = idx & 3;
            int j   = (idx >> 2) & (NJ - 1);
            int tap = idx >> 7;
            *(uint4*)(sm + SM_B + tap * BT_STR + j * RSTR + q * 16) =
                wsrc[(size_t)(tap * Jc + nh * NJ + j) * 4 + q];
        }
    }
    __syncthreads();

    // ---- MMA mainloop: warp w -> M rows [w*64, w*64+64), N=32
    const int m0 = wid * 64;
    float d[4][4][4];
#pragma unroll
    for (int mt = 0; mt < 4; ++mt)
#pragma unroll
        for (int nt = 0; nt < 4; ++nt)
#pragma unroll
            for (int k = 0; k < 4; ++k) d[mt][nt][k] = 0.0f;

    const int arow  = (lane & 7) + ((lane >> 3) & 1) * 8;
    const int akoff = (lane >> 4) * 16;
    const int brow  = (lane & 7) + (lane >> 4) * 8;
    const int bkoff = ((lane >> 3) & 1) * 16;

    const uint32_t aBase = smA + (m0 + arow) * RSTR + akoff;
    const uint32_t bBase = smB + brow * RSTR + bkoff;

#pragma unroll
    for (int ky = 0; ky < 3; ++ky) {
#pragma unroll
        for (int kx = 0; kx < 3; ++kx) {
            const int dlt = ky * PCOLS + kx;
            const uint32_t btap = bBase + (ky * 3 + kx) * BT_STR;
#pragma unroll
            for (int ks = 0; ks < 2; ++ks) {
                uint32_t af[4][4];
#pragma unroll
                for (int mt = 0; mt < 4; ++mt)
                    LDMX4(af[mt][0], af[mt][1], af[mt][2], af[mt][3],
                          aBase + (mt * 16 + dlt) * RSTR + ks * 32);
                uint32_t bf[4][2];
#pragma unroll
                for (int np = 0; np < 2; ++np)
                    LDMX4(bf[2 * np][0], bf[2 * np][1], bf[2 * np + 1][0], bf[2 * np + 1][1],
                          btap + np * 16 * RSTR + ks * 32);
#pragma unroll
                for (int mt = 0; mt < 4; ++mt)
#pragma unroll
                    for (int nt = 0; nt < 4; ++nt)
                        MMA16816(d[mt][nt], af[mt][0], af[mt][1], af[mt][2], af[mt][3],
                                 bf[nt][0], bf[nt][1]);
            }
        }
    }

    // ---- Epilogue: transpose via smem, vectorized coalesced stores
    __syncthreads();
    float* smO = (float*)sm;
#pragma unroll
    for (int mt = 0; mt < 4; ++mt) {
        int row = m0 + mt * 16 + (lane >> 2);
#pragma unroll
        for (int nt = 0; nt < 4; ++nt) {
            int j = nt * 8 + (lane & 3) * 2;
            smO[j * OSTR + row]           = d[mt][nt][0];
            smO[(j + 1) * OSTR + row]     = d[mt][nt][1];
            smO[j * OSTR + row + 8]       = d[mt][nt][2];
            smO[(j + 1) * OSTR + row + 8] = d[mt][nt][3];
        }
    }
    __syncthreads();

    {
        float* obase = out + ((size_t)b * (G * Jc) + g * Jc + nh * NJ) * HW
                           + (size_t)r0 * Wc;
        for (int idx = tid; idx < NJ * TILE_OR * 14; idx += NTHREADS) {
            int jl   = idx / (TILE_OR * 14);
            int rem  = idx - jl * (TILE_OR * 14);
            int orow = rem / 14;
            int q    = rem - orow * 14;
            float4 v = *(const float4*)(smO + jl * OSTR + orow * PCOLS + q * 4);
            float bv = bias_s[jl];
            v.x += bv; v.y += bv; v.z += bv; v.w += bv;
            *(float4*)(obase + (size_t)jl * HW + orow * Wc + q * 4) = v;
        }
    }
}

extern "C" void kernel_launch(void* const* d_in, const int* in_sizes, int n_in,
                              void* d_out, int out_size)
{
    const float* x    = (const float*)d_in[0];
    const float* wgt  = (const float*)d_in[1];
    const float* bias = (const float*)d_in[2];
    const int*   arr  = (const int*)d_in[3];
    float* out = (float*)d_out;

    prep_kernel<<<dim3(G, XP_YBLK + 1, Bc), 256>>>(x, wgt, arr);  // 7168 blocks

    cudaFuncSetAttribute(grouped_conv_hmma_kernel,
                         cudaFuncAttributeMaxDynamicSharedMemorySize, SMEM_BYTES);

    dim3 grid(G * 2, Hc / TILE_OR, Bc);   // (16, 7, 16) = 1792 blocks
    grouped_conv_hmma_kernel<<<grid, NTHREADS, SMEM_BYTES>>>(bias, out);
}